// round 1
// baseline (speedup 1.0000x reference)
#include <cuda_runtime.h>
#include <math.h>

// Problem constants
#define Bz   2
#define Lz   2048
#define Ez   1024
#define Hz   16
#define Dz   64
#define BLz  (Bz*Lz)          // 4096 rows
#define E3z  (3*Ez)           // 3072
#define FFz  (4*Ez)           // 4096

// ---------------- static device scratch (no allocations allowed) ----------------
__device__ float g_h  [(long long)BLz*Ez];        // 16 MB  layernorm output
__device__ float g_qkv[(long long)BLz*E3z];       // 48 MB  fused qkv
__device__ float g_S  [(long long)Bz*Hz*Lz*Lz];   // 512 MB attention scores
__device__ float g_att[(long long)BLz*Ez];        // 16 MB  attention output (B,L,E)
__device__ float g_x1 [(long long)BLz*Ez];        // 16 MB  x after attn residual
__device__ float g_ffn[(long long)BLz*FFz];       // 64 MB  gelu(h@W1+b1)

// ---------------- GEMM: 128x128 tile, BK=8, 256 threads, 8x8/thread ----------------
// Assumes M % 128 == 0 and K % 8 == 0 (true for every call here). N is guarded.
enum { EPI_NONE = 0, EPI_BIAS_RES = 1, EPI_BIAS_GELU = 2 };

template<bool TRANSB, int EPI>
__global__ __launch_bounds__(256) void gemm_k(
    const float* __restrict__ A, const float* __restrict__ B, float* __restrict__ C,
    const float* __restrict__ bias, const float* __restrict__ res,
    int M, int N, int K, int lda, int ldb, int ldc,
    int NH,
    long long sAb, long long sAh,
    long long sBb, long long sBh,
    long long sCb, long long sCh)
{
    int z  = blockIdx.z;
    int bb = z / NH, hh = z % NH;
    A += bb * sAb + hh * sAh;
    B += bb * sBb + hh * sBh;
    C += bb * sCb + hh * sCh;
    const float* resp = res;
    if (EPI == EPI_BIAS_RES) resp = res + bb * sCb + hh * sCh;

    __shared__ float As[8][128];
    __shared__ float Bs[8][128];

    int tid = threadIdx.x;
    int tx = tid & 15, ty = tid >> 4;
    int m0 = blockIdx.y * 128, n0 = blockIdx.x * 128;

    float acc[8][8];
    #pragma unroll
    for (int i = 0; i < 8; i++)
        #pragma unroll
        for (int j = 0; j < 8; j++) acc[i][j] = 0.f;

    int arow = tid >> 1, acol = (tid & 1) * 4;     // A-tile: 128 rows x 8 k
    int brow = tid >> 5, bcol = (tid & 31) * 4;    // B-tile NN: 8 k x 128 cols

    for (int k0 = 0; k0 < K; k0 += 8) {
        float4 av = *reinterpret_cast<const float4*>(
            &A[(long long)(m0 + arow) * lda + k0 + acol]);
        As[acol + 0][arow] = av.x; As[acol + 1][arow] = av.y;
        As[acol + 2][arow] = av.z; As[acol + 3][arow] = av.w;

        if (!TRANSB) {
            float4 bv = make_float4(0.f, 0.f, 0.f, 0.f);
            if (n0 + bcol < N)
                bv = *reinterpret_cast<const float4*>(
                    &B[(long long)(k0 + brow) * ldb + n0 + bcol]);
            *reinterpret_cast<float4*>(&Bs[brow][bcol]) = bv;
        } else {
            float4 bv = make_float4(0.f, 0.f, 0.f, 0.f);
            if (n0 + arow < N)
                bv = *reinterpret_cast<const float4*>(
                    &B[(long long)(n0 + arow) * ldb + k0 + acol]);
            Bs[acol + 0][arow] = bv.x; Bs[acol + 1][arow] = bv.y;
            Bs[acol + 2][arow] = bv.z; Bs[acol + 3][arow] = bv.w;
        }
        __syncthreads();

        #pragma unroll
        for (int kk = 0; kk < 8; kk++) {
            float a[8], b[8];
            *reinterpret_cast<float4*>(&a[0]) = *reinterpret_cast<const float4*>(&As[kk][ty * 4]);
            *reinterpret_cast<float4*>(&a[4]) = *reinterpret_cast<const float4*>(&As[kk][64 + ty * 4]);
            *reinterpret_cast<float4*>(&b[0]) = *reinterpret_cast<const float4*>(&Bs[kk][tx * 4]);
            *reinterpret_cast<float4*>(&b[4]) = *reinterpret_cast<const float4*>(&Bs[kk][64 + tx * 4]);
            #pragma unroll
            for (int i = 0; i < 8; i++)
                #pragma unroll
                for (int j = 0; j < 8; j++)
                    acc[i][j] += a[i] * b[j];
        }
        __syncthreads();
    }

    #pragma unroll
    for (int i = 0; i < 8; i++) {
        int r = m0 + ((i < 4) ? (ty * 4 + i) : (64 + ty * 4 + i - 4));
        #pragma unroll
        for (int j = 0; j < 8; j++) {
            int c = n0 + ((j < 4) ? (tx * 4 + j) : (64 + tx * 4 + j - 4));
            if (c < N) {
                float v = acc[i][j];
                if (EPI == EPI_BIAS_RES)
                    v += bias[c] + resp[(long long)r * ldc + c];
                if (EPI == EPI_BIAS_GELU) {
                    v += bias[c];
                    v = 0.5f * v * (1.f + erff(v * 0.70710678118654752f));
                }
                C[(long long)r * ldc + c] = v;
            }
        }
    }
}

// ---------------- LayerNorm: one block per row of E=1024 ----------------
__global__ __launch_bounds__(256) void ln_k(
    const float* __restrict__ x, const float* __restrict__ g,
    const float* __restrict__ b, float* __restrict__ y)
{
    __shared__ float sh_s[8];
    __shared__ float sh_q[8];
    long long row = blockIdx.x;
    const float* xr = x + row * Ez;
    int t = threadIdx.x;

    float4 v = reinterpret_cast<const float4*>(xr)[t];
    float s  = v.x + v.y + v.z + v.w;
    float sq = v.x * v.x + v.y * v.y + v.z * v.z + v.w * v.w;
    #pragma unroll
    for (int o = 16; o > 0; o >>= 1) {
        s  += __shfl_down_sync(0xffffffffu, s,  o);
        sq += __shfl_down_sync(0xffffffffu, sq, o);
    }
    int warp = t >> 5, lane = t & 31;
    if (lane == 0) { sh_s[warp] = s; sh_q[warp] = sq; }
    __syncthreads();
    if (warp == 0) {
        s  = (lane < 8) ? sh_s[lane] : 0.f;
        sq = (lane < 8) ? sh_q[lane] : 0.f;
        #pragma unroll
        for (int o = 4; o > 0; o >>= 1) {
            s  += __shfl_down_sync(0xffffffffu, s,  o);
            sq += __shfl_down_sync(0xffffffffu, sq, o);
        }
        if (lane == 0) { sh_s[0] = s; sh_q[0] = sq; }
    }
    __syncthreads();
    float mu  = sh_s[0] * (1.f / Ez);
    float var = sh_q[0] * (1.f / Ez) - mu * mu;
    float inv = rsqrtf(var + 1e-5f);

    int c = t * 4;
    float4 gg = reinterpret_cast<const float4*>(g)[t];
    float4 bb = reinterpret_cast<const float4*>(b)[t];
    float4 o;
    o.x = (v.x - mu) * inv * gg.x + bb.x;
    o.y = (v.y - mu) * inv * gg.y + bb.y;
    o.z = (v.z - mu) * inv * gg.z + bb.z;
    o.w = (v.w - mu) * inv * gg.w + bb.w;
    reinterpret_cast<float4*>(y + row * Ez)[t] = o;
    (void)c;
}

// ---------------- Softmax over rows of 2048 with 1/sqrt(E)=1/32 scale ----------------
__global__ __launch_bounds__(256) void softmax_k(float* __restrict__ S)
{
    __shared__ float sh[8];
    long long row = blockIdx.x;
    float* p = S + row * (long long)Lz;
    int t = threadIdx.x;
    const float scale = 1.f / 32.f;

    float4 v0 = reinterpret_cast<const float4*>(p)[t];
    float4 v1 = reinterpret_cast<const float4*>(p)[t + 256];

    float m = fmaxf(fmaxf(fmaxf(v0.x, v0.y), fmaxf(v0.z, v0.w)),
                    fmaxf(fmaxf(v1.x, v1.y), fmaxf(v1.z, v1.w)));
    #pragma unroll
    for (int o = 16; o > 0; o >>= 1) m = fmaxf(m, __shfl_down_sync(0xffffffffu, m, o));
    int warp = t >> 5, lane = t & 31;
    if (lane == 0) sh[warp] = m;
    __syncthreads();
    if (warp == 0) {
        m = (lane < 8) ? sh[lane] : -INFINITY;
        #pragma unroll
        for (int o = 4; o > 0; o >>= 1) m = fmaxf(m, __shfl_down_sync(0xffffffffu, m, o));
        if (lane == 0) sh[0] = m;
    }
    __syncthreads();
    m = sh[0];
    __syncthreads();

    v0.x = expf((v0.x - m) * scale); v0.y = expf((v0.y - m) * scale);
    v0.z = expf((v0.z - m) * scale); v0.w = expf((v0.w - m) * scale);
    v1.x = expf((v1.x - m) * scale); v1.y = expf((v1.y - m) * scale);
    v1.z = expf((v1.z - m) * scale); v1.w = expf((v1.w - m) * scale);

    float s = v0.x + v0.y + v0.z + v0.w + v1.x + v1.y + v1.z + v1.w;
    #pragma unroll
    for (int o = 16; o > 0; o >>= 1) s += __shfl_down_sync(0xffffffffu, s, o);
    if (lane == 0) sh[warp] = s;
    __syncthreads();
    if (warp == 0) {
        s = (lane < 8) ? sh[lane] : 0.f;
        #pragma unroll
        for (int o = 4; o > 0; o >>= 1) s += __shfl_down_sync(0xffffffffu, s, o);
        if (lane == 0) sh[0] = s;
    }
    __syncthreads();
    float r = 1.f / sh[0];

    v0.x *= r; v0.y *= r; v0.z *= r; v0.w *= r;
    v1.x *= r; v1.y *= r; v1.z *= r; v1.w *= r;
    reinterpret_cast<float4*>(p)[t]       = v0;
    reinterpret_cast<float4*>(p)[t + 256] = v1;
}

// ---------------- driver ----------------
extern "C" void kernel_launch(void* const* d_in, const int* in_sizes, int n_in,
                              void* d_out, int out_size)
{
    (void)in_sizes; (void)n_in; (void)out_size;
    const float* x      = (const float*)d_in[0];
    const float* ln1_g  = (const float*)d_in[1];
    const float* ln1_b  = (const float*)d_in[2];
    const float* W_qkv  = (const float*)d_in[3];
    const float* W_proj = (const float*)d_in[4];
    const float* b_proj = (const float*)d_in[5];
    const float* ln2_g  = (const float*)d_in[6];
    const float* ln2_b  = (const float*)d_in[7];
    const float* W1     = (const float*)d_in[8];
    const float* b1     = (const float*)d_in[9];
    const float* W2     = (const float*)d_in[10];
    const float* b2     = (const float*)d_in[11];
    float* out = (float*)d_out;

    float *h, *qkv, *S, *att, *x1, *ffn;
    cudaGetSymbolAddress((void**)&h,   g_h);
    cudaGetSymbolAddress((void**)&qkv, g_qkv);
    cudaGetSymbolAddress((void**)&S,   g_S);
    cudaGetSymbolAddress((void**)&att, g_att);
    cudaGetSymbolAddress((void**)&x1,  g_x1);
    cudaGetSymbolAddress((void**)&ffn, g_ffn);

    // 1. h = LN1(x)
    ln_k<<<BLz, 256>>>(x, ln1_g, ln1_b, h);

    // 2. qkv = h @ W_qkv              [4096,1024]x[1024,3072]
    gemm_k<false, EPI_NONE><<<dim3(E3z / 128, BLz / 128, 1), 256>>>(
        h, W_qkv, qkv, nullptr, nullptr,
        BLz, E3z, Ez, Ez, E3z, E3z, 1, 0, 0, 0, 0, 0, 0);

    // 3. S = Q @ K^T (batched over b,h)  M=N=2048, K=64
    gemm_k<true, EPI_NONE><<<dim3(Lz / 128, Lz / 128, Bz * Hz), 256>>>(
        qkv,            /* Q view */
        qkv + Ez,       /* K view */
        S, nullptr, nullptr,
        Lz, Lz, Dz, E3z, E3z, Lz, Hz,
        (long long)Lz * E3z, Dz,                 /* A strides (b,h) */
        (long long)Lz * E3z, Dz,                 /* B strides */
        (long long)Hz * Lz * Lz, (long long)Lz * Lz);

    // 4. softmax rows (scale 1/32 inside)
    softmax_k<<<Bz * Hz * Lz, 256>>>(S);

    // 5. att = P @ V  (batched) M=2048, N=64, K=2048; writes [B,L,E] layout
    gemm_k<false, EPI_NONE><<<dim3(1, Lz / 128, Bz * Hz), 256>>>(
        S, qkv + 2 * Ez, att, nullptr, nullptr,
        Lz, Dz, Lz, Lz, E3z, Ez, Hz,
        (long long)Hz * Lz * Lz, (long long)Lz * Lz,
        (long long)Lz * E3z, Dz,
        (long long)Lz * Ez, Dz);

    // 6. x1 = x + att @ W_proj + b_proj
    gemm_k<false, EPI_BIAS_RES><<<dim3(Ez / 128, BLz / 128, 1), 256>>>(
        att, W_proj, x1, b_proj, x,
        BLz, Ez, Ez, Ez, Ez, Ez, 1, 0, 0, 0, 0, 0, 0);

    // 7. h = LN2(x1)
    ln_k<<<BLz, 256>>>(x1, ln2_g, ln2_b, h);

    // 8. ffn = gelu(h @ W1 + b1)      [4096,1024]x[1024,4096]
    gemm_k<false, EPI_BIAS_GELU><<<dim3(FFz / 128, BLz / 128, 1), 256>>>(
        h, W1, ffn, b1, nullptr,
        BLz, FFz, Ez, Ez, FFz, FFz, 1, 0, 0, 0, 0, 0, 0);

    // 9. out = x1 + ffn @ W2 + b2     [4096,4096]x[4096,1024]
    gemm_k<false, EPI_BIAS_RES><<<dim3(Ez / 128, BLz / 128, 1), 256>>>(
        ffn, W2, out, b2, x1,
        BLz, Ez, FFz, FFz, Ez, Ez, 1, 0, 0, 0, 0, 0, 0);
}

// round 2
// speedup vs baseline: 1.0008x; 1.0008x over previous
#include <cuda_runtime.h>
#include <math.h>

// Problem constants
#define Bz   2
#define Lz   2048
#define Ez   1024
#define Hz   16
#define Dz   64
#define BLz  (Bz*Lz)          // 4096 rows
#define E3z  (3*Ez)           // 3072
#define FFz  (4*Ez)           // 4096

// ---------------- static device scratch (no allocations allowed) ----------------
__device__ float g_h  [(long long)BLz*Ez];        // 16 MB  layernorm output
__device__ float g_qkv[(long long)BLz*E3z];       // 48 MB  fused qkv
__device__ float g_S  [(long long)Bz*Hz*Lz*Lz];   // 512 MB attention scores
__device__ float g_att[(long long)BLz*Ez];        // 16 MB  attention output (B,L,E)
__device__ float g_x1 [(long long)BLz*Ez];        // 16 MB  x after attn residual
__device__ float g_ffn[(long long)BLz*FFz];       // 64 MB  gelu(h@W1+b1)

// ---------------- GEMM: 128x128 tile, BK=8, 256 threads, 8x8/thread ----------------
// Assumes M % 128 == 0 and K % 8 == 0 (true for every call here). N is guarded.
enum { EPI_NONE = 0, EPI_BIAS_RES = 1, EPI_BIAS_GELU = 2 };

template<bool TRANSB, int EPI>
__global__ __launch_bounds__(256) void gemm_k(
    const float* __restrict__ A, const float* __restrict__ B, float* __restrict__ C,
    const float* __restrict__ bias, const float* __restrict__ res,
    int M, int N, int K, int lda, int ldb, int ldc,
    int NH,
    long long sAb, long long sAh,
    long long sBb, long long sBh,
    long long sCb, long long sCh)
{
    int z  = blockIdx.z;
    int bb = z / NH, hh = z % NH;
    A += bb * sAb + hh * sAh;
    B += bb * sBb + hh * sBh;
    C += bb * sCb + hh * sCh;
    const float* resp = res;
    if (EPI == EPI_BIAS_RES) resp = res + bb * sCb + hh * sCh;

    __shared__ float As[8][128];
    __shared__ float Bs[8][128];

    int tid = threadIdx.x;
    int tx = tid & 15, ty = tid >> 4;
    int m0 = blockIdx.y * 128, n0 = blockIdx.x * 128;

    float acc[8][8];
    #pragma unroll
    for (int i = 0; i < 8; i++)
        #pragma unroll
        for (int j = 0; j < 8; j++) acc[i][j] = 0.f;

    int arow = tid >> 1, acol = (tid & 1) * 4;     // A-tile: 128 rows x 8 k
    int brow = tid >> 5, bcol = (tid & 31) * 4;    // B-tile NN: 8 k x 128 cols

    for (int k0 = 0; k0 < K; k0 += 8) {
        float4 av = *reinterpret_cast<const float4*>(
            &A[(long long)(m0 + arow) * lda + k0 + acol]);
        As[acol + 0][arow] = av.x; As[acol + 1][arow] = av.y;
        As[acol + 2][arow] = av.z; As[acol + 3][arow] = av.w;

        if (!TRANSB) {
            float4 bv = make_float4(0.f, 0.f, 0.f, 0.f);
            if (n0 + bcol < N)
                bv = *reinterpret_cast<const float4*>(
                    &B[(long long)(k0 + brow) * ldb + n0 + bcol]);
            *reinterpret_cast<float4*>(&Bs[brow][bcol]) = bv;
        } else {
            float4 bv = make_float4(0.f, 0.f, 0.f, 0.f);
            if (n0 + arow < N)
                bv = *reinterpret_cast<const float4*>(
                    &B[(long long)(n0 + arow) * ldb + k0 + acol]);
            Bs[acol + 0][arow] = bv.x; Bs[acol + 1][arow] = bv.y;
            Bs[acol + 2][arow] = bv.z; Bs[acol + 3][arow] = bv.w;
        }
        __syncthreads();

        #pragma unroll
        for (int kk = 0; kk < 8; kk++) {
            float a[8], b[8];
            *reinterpret_cast<float4*>(&a[0]) = *reinterpret_cast<const float4*>(&As[kk][ty * 4]);
            *reinterpret_cast<float4*>(&a[4]) = *reinterpret_cast<const float4*>(&As[kk][64 + ty * 4]);
            *reinterpret_cast<float4*>(&b[0]) = *reinterpret_cast<const float4*>(&Bs[kk][tx * 4]);
            *reinterpret_cast<float4*>(&b[4]) = *reinterpret_cast<const float4*>(&Bs[kk][64 + tx * 4]);
            #pragma unroll
            for (int i = 0; i < 8; i++)
                #pragma unroll
                for (int j = 0; j < 8; j++)
                    acc[i][j] += a[i] * b[j];
        }
        __syncthreads();
    }

    #pragma unroll
    for (int i = 0; i < 8; i++) {
        int r = m0 + ((i < 4) ? (ty * 4 + i) : (64 + ty * 4 + i - 4));
        #pragma unroll
        for (int j = 0; j < 8; j++) {
            int c = n0 + ((j < 4) ? (tx * 4 + j) : (64 + tx * 4 + j - 4));
            if (c < N) {
                float v = acc[i][j];
                if (EPI == EPI_BIAS_RES)
                    v += bias[c] + resp[(long long)r * ldc + c];
                if (EPI == EPI_BIAS_GELU) {
                    v += bias[c];
                    v = 0.5f * v * (1.f + erff(v * 0.70710678118654752f));
                }
                C[(long long)r * ldc + c] = v;
            }
        }
    }
}

// ---------------- LayerNorm: one block per row of E=1024 ----------------
__global__ __launch_bounds__(256) void ln_k(
    const float* __restrict__ x, const float* __restrict__ g,
    const float* __restrict__ b, float* __restrict__ y)
{
    __shared__ float sh_s[8];
    __shared__ float sh_q[8];
    long long row = blockIdx.x;
    const float* xr = x + row * Ez;
    int t = threadIdx.x;

    float4 v = reinterpret_cast<const float4*>(xr)[t];
    float s  = v.x + v.y + v.z + v.w;
    float sq = v.x * v.x + v.y * v.y + v.z * v.z + v.w * v.w;
    #pragma unroll
    for (int o = 16; o > 0; o >>= 1) {
        s  += __shfl_down_sync(0xffffffffu, s,  o);
        sq += __shfl_down_sync(0xffffffffu, sq, o);
    }
    int warp = t >> 5, lane = t & 31;
    if (lane == 0) { sh_s[warp] = s; sh_q[warp] = sq; }
    __syncthreads();
    if (warp == 0) {
        s  = (lane < 8) ? sh_s[lane] : 0.f;
        sq = (lane < 8) ? sh_q[lane] : 0.f;
        #pragma unroll
        for (int o = 4; o > 0; o >>= 1) {
            s  += __shfl_down_sync(0xffffffffu, s,  o);
            sq += __shfl_down_sync(0xffffffffu, sq, o);
        }
        if (lane == 0) { sh_s[0] = s; sh_q[0] = sq; }
    }
    __syncthreads();
    float mu  = sh_s[0] * (1.f / Ez);
    float var = sh_q[0] * (1.f / Ez) - mu * mu;
    float inv = rsqrtf(var + 1e-5f);

    int c = t * 4;
    float4 gg = reinterpret_cast<const float4*>(g)[t];
    float4 bb = reinterpret_cast<const float4*>(b)[t];
    float4 o;
    o.x = (v.x - mu) * inv * gg.x + bb.x;
    o.y = (v.y - mu) * inv * gg.y + bb.y;
    o.z = (v.z - mu) * inv * gg.z + bb.z;
    o.w = (v.w - mu) * inv * gg.w + bb.w;
    reinterpret_cast<float4*>(y + row * Ez)[t] = o;
    (void)c;
}

// ---------------- Softmax over rows of 2048 with 1/sqrt(E)=1/32 scale ----------------
__global__ __launch_bounds__(256) void softmax_k(float* __restrict__ S)
{
    __shared__ float sh[8];
    long long row = blockIdx.x;
    float* p = S + row * (long long)Lz;
    int t = threadIdx.x;
    const float scale = 1.f / 32.f;

    float4 v0 = reinterpret_cast<const float4*>(p)[t];
    float4 v1 = reinterpret_cast<const float4*>(p)[t + 256];

    float m = fmaxf(fmaxf(fmaxf(v0.x, v0.y), fmaxf(v0.z, v0.w)),
                    fmaxf(fmaxf(v1.x, v1.y), fmaxf(v1.z, v1.w)));
    #pragma unroll
    for (int o = 16; o > 0; o >>= 1) m = fmaxf(m, __shfl_down_sync(0xffffffffu, m, o));
    int warp = t >> 5, lane = t & 31;
    if (lane == 0) sh[warp] = m;
    __syncthreads();
    if (warp == 0) {
        m = (lane < 8) ? sh[lane] : -INFINITY;
        #pragma unroll
        for (int o = 4; o > 0; o >>= 1) m = fmaxf(m, __shfl_down_sync(0xffffffffu, m, o));
        if (lane == 0) sh[0] = m;
    }
    __syncthreads();
    m = sh[0];
    __syncthreads();

    v0.x = expf((v0.x - m) * scale); v0.y = expf((v0.y - m) * scale);
    v0.z = expf((v0.z - m) * scale); v0.w = expf((v0.w - m) * scale);
    v1.x = expf((v1.x - m) * scale); v1.y = expf((v1.y - m) * scale);
    v1.z = expf((v1.z - m) * scale); v1.w = expf((v1.w - m) * scale);

    float s = v0.x + v0.y + v0.z + v0.w + v1.x + v1.y + v1.z + v1.w;
    #pragma unroll
    for (int o = 16; o > 0; o >>= 1) s += __shfl_down_sync(0xffffffffu, s, o);
    if (lane == 0) sh[warp] = s;
    __syncthreads();
    if (warp == 0) {
        s = (lane < 8) ? sh[lane] : 0.f;
        #pragma unroll
        for (int o = 4; o > 0; o >>= 1) s += __shfl_down_sync(0xffffffffu, s, o);
        if (lane == 0) sh[0] = s;
    }
    __syncthreads();
    float r = 1.f / sh[0];

    v0.x *= r; v0.y *= r; v0.z *= r; v0.w *= r;
    v1.x *= r; v1.y *= r; v1.z *= r; v1.w *= r;
    reinterpret_cast<float4*>(p)[t]       = v0;
    reinterpret_cast<float4*>(p)[t + 256] = v1;
}

// ---------------- driver ----------------
extern "C" void kernel_launch(void* const* d_in, const int* in_sizes, int n_in,
                              void* d_out, int out_size)
{
    (void)in_sizes; (void)n_in; (void)out_size;
    const float* x      = (const float*)d_in[0];
    const float* ln1_g  = (const float*)d_in[1];
    const float* ln1_b  = (const float*)d_in[2];
    const float* W_qkv  = (const float*)d_in[3];
    const float* W_proj = (const float*)d_in[4];
    const float* b_proj = (const float*)d_in[5];
    const float* ln2_g  = (const float*)d_in[6];
    const float* ln2_b  = (const float*)d_in[7];
    const float* W1     = (const float*)d_in[8];
    const float* b1     = (const float*)d_in[9];
    const float* W2     = (const float*)d_in[10];
    const float* b2     = (const float*)d_in[11];
    float* out = (float*)d_out;

    float *h, *qkv, *S, *att, *x1, *ffn;
    cudaGetSymbolAddress((void**)&h,   g_h);
    cudaGetSymbolAddress((void**)&qkv, g_qkv);
    cudaGetSymbolAddress((void**)&S,   g_S);
    cudaGetSymbolAddress((void**)&att, g_att);
    cudaGetSymbolAddress((void**)&x1,  g_x1);
    cudaGetSymbolAddress((void**)&ffn, g_ffn);

    // 1. h = LN1(x)
    ln_k<<<BLz, 256>>>(x, ln1_g, ln1_b, h);

    // 2. qkv = h @ W_qkv              [4096,1024]x[1024,3072]
    gemm_k<false, EPI_NONE><<<dim3(E3z / 128, BLz / 128, 1), 256>>>(
        h, W_qkv, qkv, nullptr, nullptr,
        BLz, E3z, Ez, Ez, E3z, E3z, 1, 0, 0, 0, 0, 0, 0);

    // 3. S = Q @ K^T (batched over b,h)  M=N=2048, K=64
    gemm_k<true, EPI_NONE><<<dim3(Lz / 128, Lz / 128, Bz * Hz), 256>>>(
        qkv,            /* Q view */
        qkv + Ez,       /* K view */
        S, nullptr, nullptr,
        Lz, Lz, Dz, E3z, E3z, Lz, Hz,
        (long long)Lz * E3z, Dz,                 /* A strides (b,h) */
        (long long)Lz * E3z, Dz,                 /* B strides */
        (long long)Hz * Lz * Lz, (long long)Lz * Lz);

    // 4. softmax rows (scale 1/32 inside)
    softmax_k<<<Bz * Hz * Lz, 256>>>(S);

    // 5. att = P @ V  (batched) M=2048, N=64, K=2048; writes [B,L,E] layout
    gemm_k<false, EPI_NONE><<<dim3(1, Lz / 128, Bz * Hz), 256>>>(
        S, qkv + 2 * Ez, att, nullptr, nullptr,
        Lz, Dz, Lz, Lz, E3z, Ez, Hz,
        (long long)Hz * Lz * Lz, (long long)Lz * Lz,
        (long long)Lz * E3z, Dz,
        (long long)Lz * Ez, Dz);

    // 6. x1 = x + att @ W_proj + b_proj
    gemm_k<false, EPI_BIAS_RES><<<dim3(Ez / 128, BLz / 128, 1), 256>>>(
        att, W_proj, x1, b_proj, x,
        BLz, Ez, Ez, Ez, Ez, Ez, 1, 0, 0, 0, 0, 0, 0);

    // 7. h = LN2(x1)
    ln_k<<<BLz, 256>>>(x1, ln2_g, ln2_b, h);

    // 8. ffn = gelu(h @ W1 + b1)      [4096,1024]x[1024,4096]
    gemm_k<false, EPI_BIAS_GELU><<<dim3(FFz / 128, BLz / 128, 1), 256>>>(
        h, W1, ffn, b1, nullptr,
        BLz, FFz, Ez, Ez, FFz, FFz, 1, 0, 0, 0, 0, 0, 0);

    // 9. out = x1 + ffn @ W2 + b2     [4096,4096]x[4096,1024]
    gemm_k<false, EPI_BIAS_RES><<<dim3(Ez / 128, BLz / 128, 1), 256>>>(
        ffn, W2, out, b2, x1,
        BLz, Ez, FFz, FFz, Ez, Ez, 1, 0, 0, 0, 0, 0, 0);
}